// round 3
// baseline (speedup 1.0000x reference)
#include <cuda_runtime.h>

#define NB 8
#define NT 2048
#define ND 1024
#define NH 64
#define SPLITS 4
#define NQT (NT / 16)

typedef unsigned long long ull;

// ---------------------------------------------------------------------------
// Packed f32x2 helpers (FFMA2: 2x fp32 throughput, PTX-only on sm_103a)
// ---------------------------------------------------------------------------
__device__ __forceinline__ ull pack2(float lo, float hi) {
    ull r;
    asm("mov.b64 %0, {%1, %2};" : "=l"(r) : "f"(lo), "f"(hi));
    return r;
}
__device__ __forceinline__ ull pack2s(float v) { return pack2(v, v); }
__device__ __forceinline__ void fma2(ull& d, ull a, ull b) {
    asm("fma.rn.f32x2 %0, %1, %2, %0;" : "+l"(d) : "l"(a), "l"(b));
}
__device__ __forceinline__ void mul2(ull& d, ull a) {
    asm("mul.rn.f32x2 %0, %0, %1;" : "+l"(d) : "l"(a));
}
__device__ __forceinline__ float2 unpack2(ull v) {
    float2 r;
    asm("mov.b64 {%0, %1}, %2;" : "=f"(r.x), "=f"(r.y) : "l"(v));
    return r;
}

// Scratch: projected Q/K/V + split-K partials.
__device__ float g_q[NB * NT * NH];
__device__ float g_k[NB * NT * NH];
__device__ float g_v[NB * NT * NH];
__device__ float g_po[NB * NQT * SPLITS * 16 * NH];
__device__ float g_pm[NB * NQT * SPLITS * 16];
__device__ float g_pl[NB * NQT * SPLITS * 16];

// ---------------------------------------------------------------------------
// Projection: one 64x64 output tile of ONE matrix per block (z selects
// Wq/Wk/Wv). BK=16, 256 threads, f32x2 accumulators, reg-prefetch of the
// next global tile overlapping compute. Tiles with t0 >= L are skipped
// (their outputs are never consumed).
// ---------------------------------------------------------------------------
__global__ __launch_bounds__(256) void proj_kernel(
    const float* __restrict__ x,
    const float* __restrict__ Wq,
    const float* __restrict__ Wk,
    const float* __restrict__ Wv,
    const int* __restrict__ valid_lens)
{
    const int b  = blockIdx.y;
    const int t0 = blockIdx.x * 64;
    const int z  = blockIdx.z;
    int L = valid_lens[b];
    if (L < 0) L = 0;
    if (L > NT) L = NT;
    if (t0 >= L) return;

    const float* __restrict__ W = (z == 0) ? Wq : ((z == 1) ? Wk : Wv);
    float* __restrict__ O = (z == 0) ? g_q : ((z == 1) ? g_k : g_v);

    __shared__ __align__(16) float xs[16][72];  // [k][row], stride 72 -> conflict-free STS
    __shared__ __align__(16) float ws[16][68];  // [k][h]

    const int tid = threadIdx.x;
    const int tx  = tid & 15;   // h group (tx*4)
    const int ty  = tid >> 4;   // row group (ty*4)

    const int xr = tid >> 2;          // 0..63 row
    const int xk = (tid & 3) * 4;     // k within tile
    const int wk = tid >> 4;          // 0..15 k
    const int wh = (tid & 15) * 4;    // h

    ull acc[4][2];
    #pragma unroll
    for (int i = 0; i < 4; i++) { acc[i][0] = 0ull; acc[i][1] = 0ull; }

    const float* xp = &x[((size_t)b * NT + t0 + xr) * ND + xk];
    float4 xv = *(const float4*)xp;
    float4 wv = *(const float4*)&W[(size_t)wk * NH + wh];

    for (int kb = 0; kb < ND; kb += 16) {
        __syncthreads();
        xs[xk + 0][xr] = xv.x;
        xs[xk + 1][xr] = xv.y;
        xs[xk + 2][xr] = xv.z;
        xs[xk + 3][xr] = xv.w;
        *(float4*)&ws[wk][wh] = wv;
        if (kb + 16 < ND) {
            xv = *(const float4*)(xp + kb + 16);
            wv = *(const float4*)&W[(size_t)(kb + 16 + wk) * NH + wh];
        }
        __syncthreads();

        #pragma unroll
        for (int kk = 0; kk < 16; kk++) {
            float4 a = *(const float4*)&xs[kk][ty * 4];
            ulonglong2 bv = *(const ulonglong2*)&ws[kk][tx * 4];
            ull a0 = pack2s(a.x), a1 = pack2s(a.y), a2 = pack2s(a.z), a3 = pack2s(a.w);
            fma2(acc[0][0], a0, bv.x); fma2(acc[0][1], a0, bv.y);
            fma2(acc[1][0], a1, bv.x); fma2(acc[1][1], a1, bv.y);
            fma2(acc[2][0], a2, bv.x); fma2(acc[2][1], a2, bv.y);
            fma2(acc[3][0], a3, bv.x); fma2(acc[3][1], a3, bv.y);
        }
    }

    #pragma unroll
    for (int i = 0; i < 4; i++) {
        ulonglong2 st; st.x = acc[i][0]; st.y = acc[i][1];
        *(ulonglong2*)&O[((size_t)b * NT + t0 + ty * 4 + i) * NH + tx * 4] = st;
    }
}

// ---------------------------------------------------------------------------
// Flash-attention partials: 16 q-rows x 8 threads/row, 64-key tiles,
// split-K over SPLITS blocks (z). Writes unnormalized (m, l, o) partials.
// ---------------------------------------------------------------------------
__global__ __launch_bounds__(128) void attn_part(const int* __restrict__ valid_lens)
{
    const int b  = blockIdx.y;
    const int qt = blockIdx.x;
    const int q0 = qt * 16;
    const int s  = blockIdx.z;
    int L = valid_lens[b];
    if (L < 0) L = 0;
    if (L > NT) L = NT;

    const int tid = threadIdx.x;
    const int row = tid >> 3;
    const int t8  = tid & 7;
    const int q   = q0 + row;

    const size_t pidx = (((size_t)b * NQT + qt) * SPLITS + s) * 16 + row;
    float* __restrict__ po = &g_po[pidx * NH];

    const int kend = (q0 + 16 < L) ? (q0 + 16) : L;
    int jb = 0, je = 0;
    if (kend > 0) {
        int C = (((kend + SPLITS - 1) / SPLITS) + 63) & ~63;
        jb = s * C;
        je = (jb + C < kend) ? (jb + C) : kend;
    }
    if (jb >= je) {
        float4 zz = make_float4(0.f, 0.f, 0.f, 0.f);
        *(float4*)&po[t8 * 4]      = zz;
        *(float4*)&po[32 + t8 * 4] = zz;
        if (t8 == 0) { g_pm[pidx] = -1e30f; g_pl[pidx] = 0.f; }
        return;
    }

    __shared__ __align__(16) float Ks[64][68];
    __shared__ __align__(16) float Vs[64][68];
    __shared__ float Ps[16][72];

    // Q row as 16 packed-pair vectors (64 floats)
    const size_t obase = ((size_t)b * NT + q) * NH;
    ulonglong2 qv[16];
    #pragma unroll
    for (int i = 0; i < 16; i++)
        qv[i] = *(const ulonglong2*)&g_q[obase + i * 4];

    float m = -1e30f, l = 0.f;
    ull oA0 = 0ull, oA1 = 0ull, oB0 = 0ull, oB1 = 0ull;

    for (int j0 = jb; j0 < je; j0 += 64) {
        __syncthreads();
        #pragma unroll
        for (int i = 0; i < 8; i++) {
            int idx4 = tid + 128 * i;
            int r    = idx4 >> 4;
            int c4   = (idx4 & 15) * 4;
            size_t g = ((size_t)b * NT + j0 + r) * NH + c4;
            *(float4*)&Ks[r][c4] = *(const float4*)&g_k[g];
            *(float4*)&Vs[r][c4] = *(const float4*)&g_v[g];
        }
        __syncthreads();

        // S = q . k for 8 strided keys
        float sv[8];
        #pragma unroll
        for (int j = 0; j < 8; j++) {
            const int kk  = t8 + 8 * j;
            const int key = j0 + kk;
            ull accA = 0ull, accB = 0ull;
            #pragma unroll
            for (int h4 = 0; h4 < 16; h4++) {
                ulonglong2 kv = *(const ulonglong2*)&Ks[kk][h4 * 4];
                fma2(accA, qv[h4].x, kv.x);
                fma2(accB, qv[h4].y, kv.y);
            }
            float2 ra = unpack2(accA), rb = unpack2(accB);
            float sc = (ra.x + ra.y) + (rb.x + rb.y);
            bool valid = (key <= q) && (key < L);
            sv[j] = valid ? sc * 0.125f : -1e30f;
        }

        float tm = sv[0];
        #pragma unroll
        for (int j = 1; j < 8; j++) tm = fmaxf(tm, sv[j]);
        #pragma unroll
        for (int off = 1; off < 8; off <<= 1)
            tm = fmaxf(tm, __shfl_xor_sync(0xffffffffu, tm, off));

        const float mn   = fmaxf(m, tm);
        const float corr = __expf(m - mn);

        float psum = 0.f;
        float pj[8];
        #pragma unroll
        for (int j = 0; j < 8; j++) {
            pj[j] = (sv[j] > -1e29f) ? __expf(sv[j] - mn) : 0.f;
            psum += pj[j];
        }
        #pragma unroll
        for (int off = 1; off < 8; off <<= 1)
            psum += __shfl_xor_sync(0xffffffffu, psum, off);

        l = l * corr + psum;
        m = mn;
        const ull c2 = pack2s(corr);
        mul2(oA0, c2); mul2(oA1, c2); mul2(oB0, c2); mul2(oB1, c2);

        #pragma unroll
        for (int j = 0; j < 8; j++) Ps[row][t8 + 8 * j] = pj[j];
        __syncthreads();

        #pragma unroll 4
        for (int kk = 0; kk < 64; kk++) {
            const ull pp = pack2s(Ps[row][kk]);
            ulonglong2 v0 = *(const ulonglong2*)&Vs[kk][t8 * 4];
            ulonglong2 v1 = *(const ulonglong2*)&Vs[kk][32 + t8 * 4];
            fma2(oA0, pp, v0.x);
            fma2(oA1, pp, v0.y);
            fma2(oB0, pp, v1.x);
            fma2(oB1, pp, v1.y);
        }
    }

    ulonglong2 stA; stA.x = oA0; stA.y = oA1;
    ulonglong2 stB; stB.x = oB0; stB.y = oB1;
    *(ulonglong2*)&po[t8 * 4]      = stA;
    *(ulonglong2*)&po[32 + t8 * 4] = stB;
    if (t8 == 0) { g_pm[pidx] = m; g_pl[pidx] = l; }
}

// ---------------------------------------------------------------------------
// Combine split-K partials: out = (sum_s o_s * e^{m_s - m*}) / (sum_s l_s e^{...})
// Rows with q >= L (or no valid key) output zero.
// ---------------------------------------------------------------------------
__global__ __launch_bounds__(128) void attn_combine(
    const int* __restrict__ valid_lens, float* __restrict__ out)
{
    const int b  = blockIdx.y;
    const int qt = blockIdx.x;
    const int tid = threadIdx.x;
    const int row = tid >> 3;
    const int t8  = tid & 7;
    const int q   = qt * 16 + row;
    int L = valid_lens[b];
    if (L < 0) L = 0;
    if (L > NT) L = NT;

    const size_t base0 = (((size_t)b * NQT + qt) * SPLITS) * 16 + row;

    float ms[SPLITS];
    float mstar = -1e30f;
    #pragma unroll
    for (int s = 0; s < SPLITS; s++) {
        ms[s] = g_pm[base0 + (size_t)s * 16];
        mstar = fmaxf(mstar, ms[s]);
    }

    float l = 0.f;
    float4 oA = make_float4(0.f, 0.f, 0.f, 0.f);
    float4 oB = make_float4(0.f, 0.f, 0.f, 0.f);
    #pragma unroll
    for (int s = 0; s < SPLITS; s++) {
        const float w = (ms[s] > -1e29f) ? __expf(ms[s] - mstar) : 0.f;
        const size_t pi = base0 + (size_t)s * 16;
        l += g_pl[pi] * w;
        float4 a = *(const float4*)&g_po[pi * NH + t8 * 4];
        float4 c = *(const float4*)&g_po[pi * NH + 32 + t8 * 4];
        oA.x += a.x * w; oA.y += a.y * w; oA.z += a.z * w; oA.w += a.w * w;
        oB.x += c.x * w; oB.y += c.y * w; oB.z += c.z * w; oB.w += c.w * w;
    }

    const float inv = (q < L && l > 0.f) ? (1.f / l) : 0.f;
    const size_t obase = ((size_t)b * NT + q) * NH;
    *(float4*)&out[obase + t8 * 4] =
        make_float4(oA.x * inv, oA.y * inv, oA.z * inv, oA.w * inv);
    *(float4*)&out[obase + 32 + t8 * 4] =
        make_float4(oB.x * inv, oB.y * inv, oB.z * inv, oB.w * inv);
}

extern "C" void kernel_launch(void* const* d_in, const int* in_sizes, int n_in,
                              void* d_out, int out_size)
{
    const float* x  = (const float*)d_in[0];
    const float* Wq = (const float*)d_in[1];
    const float* Wk = (const float*)d_in[2];
    const float* Wv = (const float*)d_in[3];
    const int*   vl = (const int*)d_in[4];
    float* out = (float*)d_out;

    proj_kernel<<<dim3(NT / 64, NB, 3), 256>>>(x, Wq, Wk, Wv, vl);
    attn_part<<<dim3(NQT, NB, SPLITS), 128>>>(vl);
    attn_combine<<<dim3(NQT, NB), 128>>>(vl, out);
}

// round 4
// speedup vs baseline: 1.4506x; 1.4506x over previous
#include <cuda_runtime.h>

#define NB 8
#define NT 2048
#define ND 1024
#define NH 64
#define SPL 2

typedef unsigned long long ull;

__device__ __forceinline__ ull pack2(float lo, float hi) {
    ull r; asm("mov.b64 %0, {%1, %2};" : "=l"(r) : "f"(lo), "f"(hi)); return r;
}
__device__ __forceinline__ ull pack2s(float v) { return pack2(v, v); }
__device__ __forceinline__ void fma2(ull& d, ull a, ull b) {
    asm("fma.rn.f32x2 %0, %1, %2, %0;" : "+l"(d) : "l"(a), "l"(b));
}
__device__ __forceinline__ void mul2(ull& d, ull a) {
    asm("mul.rn.f32x2 %0, %0, %1;" : "+l"(d) : "l"(a));
}
__device__ __forceinline__ float2 unpack2(ull v) {
    float2 r; asm("mov.b64 {%0, %1}, %2;" : "=f"(r.x), "=f"(r.y) : "l"(v)); return r;
}

// Q,K stored transposed: [b][h][t]. V normal: [b][t][h]. All zero-init.
__device__ float g_qT[NB * NH * NT];
__device__ float g_kT[NB * NH * NT];
__device__ float g_v [NB * NT * NH];
__device__ float g_po[(size_t)NB * NT * SPL * NH];
__device__ float g_pm[NB * NT * SPL];
__device__ float g_pl[NB * NT * SPL];

// ---------------------------------------------------------------------------
// Projection: 64x64 tile of one matrix per block (z). 64 threads, 8x8/thread,
// row-paired f32x2 accumulators, double-buffered smem.
// ---------------------------------------------------------------------------
__global__ __launch_bounds__(64) void proj_kernel(
    const float* __restrict__ x, const float* __restrict__ Wq,
    const float* __restrict__ Wk, const float* __restrict__ Wv,
    const int* __restrict__ valid_lens)
{
    const int b  = blockIdx.y;
    const int t0 = blockIdx.x * 64;
    const int z  = blockIdx.z;
    int L = valid_lens[b];
    if (L < 0) L = 0;
    if (L > NT) L = NT;
    if (t0 >= L) return;

    const float* __restrict__ W = (z == 0) ? Wq : ((z == 1) ? Wk : Wv);

    __shared__ __align__(16) float xs[2][16][76];  // [buf][k][row] transposed
    __shared__ __align__(16) float ws[2][16][68];  // [buf][k][col]

    const int tid = threadIdx.x;
    const int tx  = tid & 7;    // col group *8
    const int ty  = tid >> 3;   // row group *8

    const int xr  = tid >> 2;          // 0..15 (+16i)
    const int xk4 = (tid & 3) * 4;
    const int wk  = tid >> 4;          // 0..3 (+4i)
    const int wc4 = (tid & 15) * 4;

    ull acc[4][8];
    #pragma unroll
    for (int i = 0; i < 4; i++)
        #pragma unroll
        for (int j = 0; j < 8; j++) acc[i][j] = 0ull;

    // preload kb=0
    #pragma unroll
    for (int i = 0; i < 4; i++) {
        int r = xr + 16 * i;
        float4 v = *(const float4*)&x[((size_t)b * NT + t0 + r) * ND + xk4];
        xs[0][xk4 + 0][r] = v.x; xs[0][xk4 + 1][r] = v.y;
        xs[0][xk4 + 2][r] = v.z; xs[0][xk4 + 3][r] = v.w;
        *(float4*)&ws[0][wk + 4 * i][wc4] = *(const float4*)&W[(size_t)(wk + 4 * i) * NH + wc4];
    }
    __syncthreads();

    int buf = 0;
    for (int kb = 0; kb < ND; kb += 16) {
        if (kb + 16 < ND) {
            const int nb = buf ^ 1;
            #pragma unroll
            for (int i = 0; i < 4; i++) {
                int r = xr + 16 * i;
                float4 v = *(const float4*)&x[((size_t)b * NT + t0 + r) * ND + kb + 16 + xk4];
                xs[nb][xk4 + 0][r] = v.x; xs[nb][xk4 + 1][r] = v.y;
                xs[nb][xk4 + 2][r] = v.z; xs[nb][xk4 + 3][r] = v.w;
                *(float4*)&ws[nb][wk + 4 * i][wc4] =
                    *(const float4*)&W[(size_t)(kb + 16 + wk + 4 * i) * NH + wc4];
            }
        }
        #pragma unroll
        for (int kk = 0; kk < 16; kk++) {
            ulonglong2 A01 = *(const ulonglong2*)&xs[buf][kk][ty * 8];
            ulonglong2 A23 = *(const ulonglong2*)&xs[buf][kk][ty * 8 + 4];
            float4 b0 = *(const float4*)&ws[buf][kk][tx * 8];
            float4 b1 = *(const float4*)&ws[buf][kk][tx * 8 + 4];
            ull ra[4] = { A01.x, A01.y, A23.x, A23.y };
            ull bb[8] = { pack2s(b0.x), pack2s(b0.y), pack2s(b0.z), pack2s(b0.w),
                          pack2s(b1.x), pack2s(b1.y), pack2s(b1.z), pack2s(b1.w) };
            #pragma unroll
            for (int i = 0; i < 4; i++)
                #pragma unroll
                for (int j = 0; j < 8; j++)
                    fma2(acc[i][j], ra[i], bb[j]);
        }
        __syncthreads();
        buf ^= 1;
    }

    if (z < 2) {  // transposed store: OT[b][col][t]
        float* __restrict__ OT = (z == 0) ? g_qT : g_kT;
        #pragma unroll
        for (int j = 0; j < 8; j++) {
            const int col = tx * 8 + j;
            float2 u0 = unpack2(acc[0][j]), u1 = unpack2(acc[1][j]);
            float2 u2 = unpack2(acc[2][j]), u3 = unpack2(acc[3][j]);
            const size_t base = ((size_t)(b * NH + col)) * NT + t0 + ty * 8;
            *(float4*)&OT[base]     = make_float4(u0.x, u0.y, u1.x, u1.y);
            *(float4*)&OT[base + 4] = make_float4(u2.x, u2.y, u3.x, u3.y);
        }
    } else {      // V row-major
        #pragma unroll
        for (int i = 0; i < 4; i++) {
            float2 u[8];
            #pragma unroll
            for (int j = 0; j < 8; j++) u[j] = unpack2(acc[i][j]);
            const size_t r0 = ((size_t)b * NT + t0 + ty * 8 + 2 * i) * NH + tx * 8;
            *(float4*)&g_v[r0]          = make_float4(u[0].x, u[1].x, u[2].x, u[3].x);
            *(float4*)&g_v[r0 + 4]      = make_float4(u[4].x, u[5].x, u[6].x, u[7].x);
            *(float4*)&g_v[r0 + NH]     = make_float4(u[0].y, u[1].y, u[2].y, u[3].y);
            *(float4*)&g_v[r0 + NH + 4] = make_float4(u[4].y, u[5].y, u[6].y, u[7].y);
        }
    }
}

// ---------------------------------------------------------------------------
// Flash-attention partials: BQ=64, BK=128, 128 threads, split-K via z.
// ---------------------------------------------------------------------------
#define OFF_QT 0                    // QsT [64h][68]
#define OFF_KT 4352                 // KsT [64h][132]
#define OFF_VS 12800                // Vs  [128k][68]
#define OFF_PS 21504                // Ps  [64r][132]
#define OFF_CR 29952                // corr[64]
#define OFF_OS OFF_KT               // Os  [64r][68] overlays KsT (dead after loop)
#define SM_FLOATS 30016
#define SM_BYTES (SM_FLOATS * 4)

__global__ void attn_part(const int* __restrict__ valid_lens)
{
    extern __shared__ float sm[];
    const int b  = blockIdx.y;
    const int q0 = blockIdx.x * 64;
    const int s  = blockIdx.z;
    int L = valid_lens[b];
    if (L < 0) L = 0;
    if (L > NT) L = NT;
    if (q0 >= L) return;  // outputs zeroed via combine guard; po/pm stay 0

    const int tid = threadIdx.x;
    const int kg  = tid & 15;          // S: 16 key groups *8
    const int rg  = tid >> 4;          // S: 8 row groups *8
    const int hg  = tid & 7;           // PV: 8 h groups *8
    const int rg2 = (tid >> 3) & 7;    // PV: 8 row groups *8
    const int ks  = tid >> 6;          // PV: key half

    const int kend = (q0 + 64 < L) ? (q0 + 64) : L;
    const int C = (((kend + SPL - 1) / SPL) + 127) & ~127;
    const int jb = s * C;
    const int je = (jb + C < kend) ? (jb + C) : kend;

    if (jb >= je) {  // empty split: write neutral partials
        const float4 z4 = make_float4(0.f, 0.f, 0.f, 0.f);
        #pragma unroll
        for (int i = 0; i < 8; i++) {
            int idx = tid + 128 * i;
            int row = idx >> 4, h4 = (idx & 15) * 4;
            *(float4*)&g_po[((size_t)(b * NT + q0 + row) * SPL + s) * NH + h4] = z4;
        }
        if (tid < 64) {
            g_pm[(size_t)(b * NT + q0 + tid) * SPL + s] = -1e30f;
            g_pl[(size_t)(b * NT + q0 + tid) * SPL + s] = 0.f;
        }
        return;
    }

    // load QsT
    #pragma unroll
    for (int i = 0; i < 8; i++) {
        int idx = tid + 128 * i;
        int h = idx >> 4, r4 = (idx & 15) * 4;
        *(float4*)&sm[OFF_QT + h * 68 + r4] =
            *(const float4*)&g_qT[(size_t)(b * NH + h) * NT + q0 + r4];
    }

    float m[8], l[8];
    #pragma unroll
    for (int i = 0; i < 8; i++) { m[i] = -1e30f; l[i] = 0.f; }
    ull o[8][4];
    #pragma unroll
    for (int i = 0; i < 8; i++)
        #pragma unroll
        for (int p = 0; p < 4; p++) o[i][p] = 0ull;

    for (int j0 = jb; j0 < je; j0 += 128) {
        __syncthreads();
        #pragma unroll
        for (int i = 0; i < 16; i++) {
            int idx = tid + 128 * i;
            int h = idx >> 5, k4 = (idx & 31) * 4;
            *(float4*)&sm[OFF_KT + h * 132 + k4] =
                *(const float4*)&g_kT[(size_t)(b * NH + h) * NT + j0 + k4];
            int key = idx >> 4, h4 = (idx & 15) * 4;
            *(float4*)&sm[OFF_VS + key * 68 + h4] =
                *(const float4*)&g_v[((size_t)b * NT + j0 + key) * NH + h4];
        }
        __syncthreads();

        // S = Q K^T  (8 rows x 8 keys per thread, key-paired)
        ull sacc[8][4];
        #pragma unroll
        for (int i = 0; i < 8; i++)
            #pragma unroll
            for (int p = 0; p < 4; p++) sacc[i][p] = 0ull;

        for (int h = 0; h < NH; h++) {
            float4 qa = *(const float4*)&sm[OFF_QT + h * 68 + rg * 8];
            float4 qb = *(const float4*)&sm[OFF_QT + h * 68 + rg * 8 + 4];
            ulonglong2 ka = *(const ulonglong2*)&sm[OFF_KT + h * 132 + kg * 8];
            ulonglong2 kb2 = *(const ulonglong2*)&sm[OFF_KT + h * 132 + kg * 8 + 4];
            ull qq[8] = { pack2s(qa.x), pack2s(qa.y), pack2s(qa.z), pack2s(qa.w),
                          pack2s(qb.x), pack2s(qb.y), pack2s(qb.z), pack2s(qb.w) };
            ull kk[4] = { ka.x, ka.y, kb2.x, kb2.y };
            #pragma unroll
            for (int i = 0; i < 8; i++)
                #pragma unroll
                for (int p = 0; p < 4; p++)
                    fma2(sacc[i][p], qq[i], kk[p]);
        }

        // softmax per row; write P (normal layout) + corr
        #pragma unroll
        for (int i = 0; i < 8; i++) {
            const int q = q0 + rg * 8 + i;
            float sv[8];
            #pragma unroll
            for (int p = 0; p < 4; p++) {
                float2 u = unpack2(sacc[i][p]);
                sv[2 * p] = u.x; sv[2 * p + 1] = u.y;
            }
            #pragma unroll
            for (int c = 0; c < 8; c++) {
                int key = j0 + kg * 8 + c;
                bool valid = (key <= q) && (key < L);
                sv[c] = valid ? sv[c] * 0.125f : -1e30f;
            }
            float tm = sv[0];
            #pragma unroll
            for (int c = 1; c < 8; c++) tm = fmaxf(tm, sv[c]);
            #pragma unroll
            for (int off = 1; off < 16; off <<= 1)
                tm = fmaxf(tm, __shfl_xor_sync(0xffffffffu, tm, off));
            const float mn = fmaxf(m[i], tm);
            const float corr = __expf(m[i] - mn);
            float pj[8], psum = 0.f;
            #pragma unroll
            for (int c = 0; c < 8; c++) {
                pj[c] = (sv[c] > -1e29f) ? __expf(sv[c] - mn) : 0.f;
                psum += pj[c];
            }
            #pragma unroll
            for (int off = 1; off < 16; off <<= 1)
                psum += __shfl_xor_sync(0xffffffffu, psum, off);
            l[i] = l[i] * corr + psum;
            m[i] = mn;
            *(float4*)&sm[OFF_PS + (rg * 8 + i) * 132 + kg * 8] =
                make_float4(pj[0], pj[1], pj[2], pj[3]);
            *(float4*)&sm[OFF_PS + (rg * 8 + i) * 132 + kg * 8 + 4] =
                make_float4(pj[4], pj[5], pj[6], pj[7]);
            if (kg == 0) sm[OFF_CR + rg * 8 + i] = corr;
        }
        __syncthreads();

        // rescale O, then O += P V over this thread's key half
        #pragma unroll
        for (int i = 0; i < 8; i++) {
            ull c2 = pack2s(sm[OFF_CR + rg2 * 8 + i]);
            #pragma unroll
            for (int p = 0; p < 4; p++) mul2(o[i][p], c2);
        }
        for (int k = 0; k < 64; k++) {
            const int key = ks * 64 + k;
            ulonglong2 va = *(const ulonglong2*)&sm[OFF_VS + key * 68 + hg * 8];
            ulonglong2 vb = *(const ulonglong2*)&sm[OFF_VS + key * 68 + hg * 8 + 4];
            ull vv[4] = { va.x, va.y, vb.x, vb.y };
            #pragma unroll
            for (int i = 0; i < 8; i++) {
                ull pp = pack2s(sm[OFF_PS + (rg2 * 8 + i) * 132 + key]);
                #pragma unroll
                for (int p = 0; p < 4; p++)
                    fma2(o[i][p], pp, vv[p]);
            }
        }
    }

    // write pm/pl (S mapping)
    if (kg == 0) {
        #pragma unroll
        for (int i = 0; i < 8; i++) {
            const size_t pi = (size_t)(b * NT + q0 + rg * 8 + i) * SPL + s;
            g_pm[pi] = m[i];
            g_pl[pi] = l[i];
        }
    }

    // merge ks halves, write po
    __syncthreads();
    if (ks == 1) {
        #pragma unroll
        for (int i = 0; i < 8; i++) {
            float2 u0 = unpack2(o[i][0]), u1 = unpack2(o[i][1]);
            float2 u2 = unpack2(o[i][2]), u3 = unpack2(o[i][3]);
            *(float4*)&sm[OFF_OS + (rg2 * 8 + i) * 68 + hg * 8] =
                make_float4(u0.x, u0.y, u1.x, u1.y);
            *(float4*)&sm[OFF_OS + (rg2 * 8 + i) * 68 + hg * 8 + 4] =
                make_float4(u2.x, u2.y, u3.x, u3.y);
        }
    }
    __syncthreads();
    if (ks == 0) {
        #pragma unroll
        for (int i = 0; i < 8; i++) {
            float2 u0 = unpack2(o[i][0]), u1 = unpack2(o[i][1]);
            float2 u2 = unpack2(o[i][2]), u3 = unpack2(o[i][3]);
            float4 s0 = *(const float4*)&sm[OFF_OS + (rg2 * 8 + i) * 68 + hg * 8];
            float4 s1 = *(const float4*)&sm[OFF_OS + (rg2 * 8 + i) * 68 + hg * 8 + 4];
            const size_t po = ((size_t)(b * NT + q0 + rg2 * 8 + i) * SPL + s) * NH + hg * 8;
            *(float4*)&g_po[po] =
                make_float4(u0.x + s0.x, u0.y + s0.y, u1.x + s0.z, u1.y + s0.w);
            *(float4*)&g_po[po + 4] =
                make_float4(u2.x + s1.x, u2.y + s1.y, u3.x + s1.z, u3.y + s1.w);
        }
    }
}

// ---------------------------------------------------------------------------
// Combine split-K partials.
// ---------------------------------------------------------------------------
__global__ __launch_bounds__(128) void attn_combine(
    const int* __restrict__ valid_lens, float* __restrict__ out)
{
    const int b   = blockIdx.y;
    const int tid = threadIdx.x;
    const int row = tid >> 3;
    const int t8  = tid & 7;
    const int q   = blockIdx.x * 16 + row;
    int L = valid_lens[b];
    if (L < 0) L = 0;
    if (L > NT) L = NT;

    const size_t base0 = (size_t)(b * NT + q) * SPL;
    float ms[SPL], mstar = -1e30f;
    #pragma unroll
    for (int s = 0; s < SPL; s++) {
        ms[s] = g_pm[base0 + s];
        mstar = fmaxf(mstar, ms[s]);
    }
    float l = 0.f;
    float4 oA = make_float4(0.f, 0.f, 0.f, 0.f);
    float4 oB = make_float4(0.f, 0.f, 0.f, 0.f);
    #pragma unroll
    for (int s = 0; s < SPL; s++) {
        const float w = (ms[s] > -1e29f) ? __expf(ms[s] - mstar) : 0.f;
        l += g_pl[base0 + s] * w;
        float4 a = *(const float4*)&g_po[(base0 + s) * NH + t8 * 4];
        float4 c = *(const float4*)&g_po[(base0 + s) * NH + 32 + t8 * 4];
        oA.x += a.x * w; oA.y += a.y * w; oA.z += a.z * w; oA.w += a.w * w;
        oB.x += c.x * w; oB.y += c.y * w; oB.z += c.z * w; oB.w += c.w * w;
    }
    const float inv = (q < L && l > 0.f) ? (1.f / l) : 0.f;
    const size_t ob = ((size_t)b * NT + q) * NH;
    *(float4*)&out[ob + t8 * 4] =
        make_float4(oA.x * inv, oA.y * inv, oA.z * inv, oA.w * inv);
    *(float4*)&out[ob + 32 + t8 * 4] =
        make_float4(oB.x * inv, oB.y * inv, oB.z * inv, oB.w * inv);
}

extern "C" void kernel_launch(void* const* d_in, const int* in_sizes, int n_in,
                              void* d_out, int out_size)
{
    const float* x  = (const float*)d_in[0];
    const float* Wq = (const float*)d_in[1];
    const float* Wk = (const float*)d_in[2];
    const float* Wv = (const float*)d_in[3];
    const int*   vl = (const int*)d_in[4];
    float* out = (float*)d_out;

    cudaFuncSetAttribute(attn_part, cudaFuncAttributeMaxDynamicSharedMemorySize, SM_BYTES);

    proj_kernel<<<dim3(NT / 64, NB, 3), 64>>>(x, Wq, Wk, Wv, vl);
    attn_part<<<dim3(NT / 64, NB, SPL), 128, SM_BYTES>>>(vl);
    attn_combine<<<dim3(NT / 16, NB), 128>>>(vl, out);
}